// round 6
// baseline (speedup 1.0000x reference)
#include <cuda_runtime.h>

#define MAXN 20000
#define MAXE 320000
#define MAXEP (MAXN + MAXE)

// ---------------- scratch (no allocs allowed) ----------------
__device__ int   g_deg[MAXN];
__device__ int   g_row[MAXN + 1];
__device__ int   g_cur[MAXN];
__device__ int   g_eid[MAXEP];
__device__ int   g_src[MAXEP];
__device__ float g_dis[MAXN];
__device__ __align__(16) float g_als[MAXN * 4];
__device__ __align__(16) float g_ald[MAXN * 4];
__device__ __align__(16) float g_als2[MAXN * 4];
__device__ __align__(16) float g_ald2[MAXN * 4];
__device__ __align__(16) float g_bufA[MAXN * 256];
__device__ __align__(16) float g_bufB[MAXN * 256];
__device__ __align__(16) float g_bufC[MAXN * 256];

// ---------------- CSR build ----------------
__global__ void k_zero(int n) {
    int i = blockIdx.x * blockDim.x + threadIdx.x;
    if (i < n) g_deg[i] = 0;
}

__global__ void k_count(const int* __restrict__ ei, int E, int EP) {
    int i = blockIdx.x * blockDim.x + threadIdx.x;
    if (i < EP) {
        int d = (i < E) ? ei[E + i] : (i - E);
        atomicAdd(&g_deg[d], 1);
    }
}

// single-block scan: thread-serial chunks + warp-shuffle block scan
__global__ __launch_bounds__(1024) void k_scan(int n) {
    __shared__ int wsum[32];
    int tid = threadIdx.x;
    int per = (n + 1023) >> 10;
    int start = tid * per;
    int end = min(start + per, n);

    int sum = 0;
    for (int i = start; i < end; i++) sum += g_deg[i];

    int lane = tid & 31, wid = tid >> 5;
    int v = sum;
#pragma unroll
    for (int d = 1; d < 32; d <<= 1) {
        int t = __shfl_up_sync(0xffffffffu, v, d);
        if (lane >= d) v += t;
    }
    if (lane == 31) wsum[wid] = v;
    __syncthreads();
    if (wid == 0) {
        int u = wsum[lane];
#pragma unroll
        for (int d = 1; d < 32; d <<= 1) {
            int t = __shfl_up_sync(0xffffffffu, u, d);
            if (lane >= d) u += t;
        }
        wsum[lane] = u;
    }
    __syncthreads();

    int off = v - sum + (wid ? wsum[wid - 1] : 0);
    int run = off;
    for (int i = start; i < end; i++) {
        int dv = g_deg[i];
        g_cur[i] = run;
        run += dv;
        g_row[i + 1] = run;
        g_dis[i] = rsqrtf((float)dv);
    }
    if (tid == 0) g_row[0] = 0;
}

__global__ void k_scatter(const int* __restrict__ ei, int E, int EP) {
    int i = blockIdx.x * blockDim.x + threadIdx.x;
    if (i < EP) {
        int d = (i < E) ? ei[E + i] : (i - E);
        int pos = atomicAdd(&g_cur[d], 1);
        g_eid[pos] = i;
    }
}

// deterministic order: sort each row's edge ids ascending; fused src fill
__global__ void k_sort_fill(const int* __restrict__ ei, int E, int n) {
    int i = blockIdx.x * blockDim.x + threadIdx.x;
    if (i >= n) return;
    int r0 = g_row[i], r1 = g_row[i + 1];
    for (int a = r0 + 1; a < r1; a++) {
        int v = g_eid[a];
        int b = a - 1;
        while (b >= r0 && g_eid[b] > v) { g_eid[b + 1] = g_eid[b]; b--; }
        g_eid[b + 1] = v;
    }
    for (int e = r0; e < r1; e++) {
        int eid = g_eid[e];
        g_src[e] = (eid < E) ? ei[eid] : (eid - E);
    }
}

// ---------------- tensor-core GEMM (3xTF32) ----------------
__device__ __forceinline__ unsigned cvt_tf32(float x) {
    unsigned r;
    asm("cvt.rna.tf32.f32 %0, %1;" : "=r"(r) : "f"(x));
    return r;
}

#define MMA_TF32(D, A0, A1, A2, A3, B0, B1)                                  \
    asm volatile(                                                            \
        "mma.sync.aligned.m16n8k8.row.col.f32.tf32.tf32.f32 "                \
        "{%0,%1,%2,%3}, {%4,%5,%6,%7}, {%8,%9}, {%0,%1,%2,%3};"              \
        : "+f"(D[0]), "+f"(D[1]), "+f"(D[2]), "+f"(D[3])                     \
        : "r"(A0), "r"(A1), "r"(A2), "r"(A3), "r"(B0), "r"(B1))

// C[M,256] = A[M,K] @ W[K,256] via 3xTF32 mma.sync (fp32-level accuracy).
// Block: 256 thr = 8 warps; tile 64 rows x 256 cols; K chunked by 16.
// DUAL=1 -> blockIdx.y selects (W1,C1).
template <int DUAL>
__global__ __launch_bounds__(256) void k_gemm256tc(const float* __restrict__ A,
                                                   const float* __restrict__ W0,
                                                   const float* __restrict__ W1,
                                                   float* __restrict__ C0,
                                                   float* __restrict__ C1,
                                                   int M, int K) {
    const float* W = (DUAL && blockIdx.y) ? W1 : W0;
    float*       C = (DUAL && blockIdx.y) ? C1 : C0;

    // A tile: 16 k-rows x 64 m-rows, (hi,lo) pairs
    __shared__ float2 Ash[16 * 64];
    // W tile: [g(2)][tig(4)][col(256)] x (b0h,b1h,b0l,b1l)
    __shared__ float  Wsh[2 * 4 * 256 * 4];

    int tid  = threadIdx.x;
    int lane = tid & 31, w = tid >> 5;
    int gid  = lane >> 2, tig = lane & 3;
    int wr   = w & 3,  wc = w >> 2;          // warp row(4) x warp col(2)
    int row0 = blockIdx.x * 64;

    float d[16][4];
#pragma unroll
    for (int i = 0; i < 16; i++)
#pragma unroll
        for (int j = 0; j < 4; j++) d[i][j] = 0.f;

    int arow = tid >> 2, akq = tid & 3;       // A staging: 64 rows x 4 float4
    int wkr  = tid >> 4, wcq = tid & 15;      // W staging: 16 k-rows x 16 cols/thread
    int wg   = wkr >> 3, r8 = wkr & 7;
    int wtig = r8 & 3,  hi4 = r8 >> 2;        // pair slot (row k vs k+4)

    for (int k0 = 0; k0 < K; k0 += 16) {
        // ---- stage A (hi/lo split once) ----
        float4 av = make_float4(0.f, 0.f, 0.f, 0.f);
        if (row0 + arow < M)
            av = *(const float4*)(A + (size_t)(row0 + arow) * K + k0 + akq * 4);
        float avv[4] = {av.x, av.y, av.z, av.w};
#pragma unroll
        for (int j = 0; j < 4; j++) {
            float x = avv[j];
            unsigned h = cvt_tf32(x);
            unsigned l = cvt_tf32(x - __uint_as_float(h));
            Ash[(akq * 4 + j) * 64 + arow] =
                make_float2(__uint_as_float(h), __uint_as_float(l));
        }
        // ---- stage W (hi/lo split + B-fragment row pairing) ----
#pragma unroll
        for (int q = 0; q < 4; q++) {
            float4 wv = *(const float4*)(W + (size_t)(k0 + wkr) * 256 + wcq * 16 + q * 4);
            float wvv[4] = {wv.x, wv.y, wv.z, wv.w};
#pragma unroll
            for (int j = 0; j < 4; j++) {
                float x = wvv[j];
                unsigned h = cvt_tf32(x);
                unsigned l = cvt_tf32(x - __uint_as_float(h));
                int col  = wcq * 16 + q * 4 + j;
                int base = ((wg * 4 + wtig) * 256 + col) * 4;
                Wsh[base + hi4]     = __uint_as_float(h);
                Wsh[base + 2 + hi4] = __uint_as_float(l);
            }
        }
        __syncthreads();

#pragma unroll
        for (int k8 = 0; k8 < 2; k8++) {
            float2 p0 = Ash[(k8 * 8 + tig)     * 64 + wr * 16 + gid];
            float2 p1 = Ash[(k8 * 8 + tig)     * 64 + wr * 16 + gid + 8];
            float2 p2 = Ash[(k8 * 8 + tig + 4) * 64 + wr * 16 + gid];
            float2 p3 = Ash[(k8 * 8 + tig + 4) * 64 + wr * 16 + gid + 8];
            unsigned a0h = __float_as_uint(p0.x), a0l = __float_as_uint(p0.y);
            unsigned a1h = __float_as_uint(p1.x), a1l = __float_as_uint(p1.y);
            unsigned a2h = __float_as_uint(p2.x), a2l = __float_as_uint(p2.y);
            unsigned a3h = __float_as_uint(p3.x), a3l = __float_as_uint(p3.y);
#pragma unroll
            for (int n8 = 0; n8 < 16; n8++) {
                float4 bb = *(const float4*)
                    &Wsh[((k8 * 4 + tig) * 256 + wc * 128 + n8 * 8 + gid) * 4];
                unsigned b0h = __float_as_uint(bb.x), b1h = __float_as_uint(bb.y);
                unsigned b0l = __float_as_uint(bb.z), b1l = __float_as_uint(bb.w);
                MMA_TF32(d[n8], a0h, a1h, a2h, a3h, b0h, b1h);
                MMA_TF32(d[n8], a0l, a1l, a2l, a3l, b0h, b1h);
                MMA_TF32(d[n8], a0h, a1h, a2h, a3h, b0l, b1l);
            }
        }
        __syncthreads();
    }

    // epilogue
    int ra = row0 + wr * 16 + gid;
    int rb = ra + 8;
#pragma unroll
    for (int n8 = 0; n8 < 16; n8++) {
        int col = wc * 128 + n8 * 8 + tig * 2;
        if (ra < M) *(float2*)&C[(size_t)ra * 256 + col] = make_float2(d[n8][0], d[n8][1]);
        if (rb < M) *(float2*)&C[(size_t)rb * 256 + col] = make_float2(d[n8][2], d[n8][3]);
    }
}

// C[M,64] = dis[r] * (A[M,K] @ W[K,64])  (prescaled for GCN aggregation)
__global__ __launch_bounds__(256) void k_gemm64(const float* __restrict__ A,
                                                const float* __restrict__ W,
                                                float* __restrict__ C, int M, int K) {
    __shared__ float Ash[64][36];
    __shared__ float Wsh[32][64];
    int tid = threadIdx.x;
    int x = tid & 15, y = tid >> 4;
    int row0 = blockIdx.x * 64;
    float acc[4][4];
#pragma unroll
    for (int i = 0; i < 4; i++)
#pragma unroll
        for (int j = 0; j < 4; j++) acc[i][j] = 0.f;

    for (int k0 = 0; k0 < K; k0 += 32) {
#pragma unroll
        for (int t = 0; t < 2; t++) {
            int idx = tid + t * 256;
            int r = idx >> 3, kq = idx & 7;
            int grow = row0 + r;
            float4 v = make_float4(0.f, 0.f, 0.f, 0.f);
            if (grow < M) v = *(const float4*)(A + (size_t)grow * K + k0 + kq * 4);
            *(float4*)&Ash[r][kq * 4] = v;
        }
#pragma unroll
        for (int t = 0; t < 2; t++) {
            int idx = tid + t * 256;
            int kr = idx >> 4, cq = idx & 15;
            *(float4*)&Wsh[kr][cq * 4] = *(const float4*)(W + (size_t)(k0 + kr) * 64 + cq * 4);
        }
        __syncthreads();
#pragma unroll
        for (int k = 0; k < 32; k++) {
            float a[4];
#pragma unroll
            for (int i = 0; i < 4; i++) a[i] = Ash[y + 16 * i][k];
            float4 wv = *(float4*)&Wsh[k][x * 4];
#pragma unroll
            for (int i = 0; i < 4; i++) {
                acc[i][0] += a[i] * wv.x; acc[i][1] += a[i] * wv.y;
                acc[i][2] += a[i] * wv.z; acc[i][3] += a[i] * wv.w;
            }
        }
        __syncthreads();
    }
#pragma unroll
    for (int i = 0; i < 4; i++) {
        int r = row0 + y + 16 * i;
        if (r < M) {
            float di = g_dis[r];
            *(float4*)(C + (size_t)r * 64 + x * 4) =
                make_float4(di * acc[i][0], di * acc[i][1], di * acc[i][2], di * acc[i][3]);
        }
    }
}

// ---------------- GCN aggregate (warp per node, float2 lanes, prescaled xw) --
__global__ void k_gcn_agg(const float* __restrict__ xw, const float* __restrict__ bias,
                          float* __restrict__ out, int n) {
    int w = (blockIdx.x * blockDim.x + threadIdx.x) >> 5;
    int lane = threadIdx.x & 31;
    if (w >= n) return;
    int r0 = g_row[w], r1 = g_row[w + 1];
    const float2* x2 = (const float2*)xw;
    float ax = 0.f, ay = 0.f;
    int e = r0;
    for (; e + 2 <= r1; e += 2) {
        int s0 = g_src[e], s1 = g_src[e + 1];
        float2 v0 = x2[(size_t)s0 * 32 + lane];
        float2 v1 = x2[(size_t)s1 * 32 + lane];
        ax += v0.x + v1.x; ay += v0.y + v1.y;
    }
    if (e < r1) {
        int s = g_src[e];
        float2 v = x2[(size_t)s * 32 + lane];
        ax += v.x; ay += v.y;
    }
    float di = g_dis[w];
    float2 b = ((const float2*)bias)[lane];
    ((float2*)out)[(size_t)w * 32 + lane] =
        make_float2(fmaxf(di * ax + b.x, 0.f), fmaxf(di * ay + b.y, 0.f));
}

// ---------------- attention prep ----------------
__device__ __forceinline__ void prep_node(const float* __restrict__ xw,
                                          const float* __restrict__ asrc,
                                          const float* __restrict__ adst,
                                          float* __restrict__ als,
                                          float* __restrict__ ald,
                                          int w, int lane) {
    const float4* xv = (const float4*)(xw + (size_t)w * 256);
    float4 x0 = xv[lane * 2], x1 = xv[lane * 2 + 1];
    const float4* sv = (const float4*)asrc;
    const float4* dv = (const float4*)adst;
    float4 a0 = sv[lane * 2], a1 = sv[lane * 2 + 1];
    float4 b0 = dv[lane * 2], b1 = dv[lane * 2 + 1];
    float ss = x0.x * a0.x + x0.y * a0.y + x0.z * a0.z + x0.w * a0.w
             + x1.x * a1.x + x1.y * a1.y + x1.z * a1.z + x1.w * a1.w;
    float dd = x0.x * b0.x + x0.y * b0.y + x0.z * b0.z + x0.w * b0.w
             + x1.x * b1.x + x1.y * b1.y + x1.z * b1.z + x1.w * b1.w;
#pragma unroll
    for (int d = 4; d; d >>= 1) {
        ss += __shfl_down_sync(0xffffffffu, ss, d);
        dd += __shfl_down_sync(0xffffffffu, dd, d);
    }
    if ((lane & 7) == 0) {
        int h = lane >> 3;
        als[(size_t)w * 4 + h] = ss;
        ald[(size_t)w * 4 + h] = dd;
    }
}

__global__ void k_prep(const float* __restrict__ xw, const float* __restrict__ asrc,
                       const float* __restrict__ adst, float* __restrict__ als,
                       float* __restrict__ ald, int n) {
    int w = (blockIdx.x * blockDim.x + threadIdx.x) >> 5;
    int lane = threadIdx.x & 31;
    if (w >= n) return;
    prep_node(xw, asrc, adst, als, ald, w, lane);
}

__global__ void k_prep_dual(const float* __restrict__ xw0, const float* __restrict__ a0s,
                            const float* __restrict__ a0d, float* __restrict__ als0,
                            float* __restrict__ ald0,
                            const float* __restrict__ xw1, const float* __restrict__ a1s,
                            const float* __restrict__ a1d, float* __restrict__ als1,
                            float* __restrict__ ald1, int n) {
    int w = (blockIdx.x * blockDim.x + threadIdx.x) >> 5;
    int lane = threadIdx.x & 31;
    if (w >= n) return;
    if (blockIdx.y == 0) prep_node(xw0, a0s, a0d, als0, ald0, w, lane);
    else                 prep_node(xw1, a1s, a1d, als1, ald1, w, lane);
}

// ---------------- GAT aggregate (warp per node, all 4 heads) ----------------
// MODE 0: concat(256)+bias+relu ; MODE 1: head-mean+bias+relu ; MODE 2: head-mean+bias
template <int MODE>
__device__ __forceinline__ void gat_node(const float* __restrict__ xw,
                                         const float* __restrict__ bias,
                                         const float* __restrict__ als,
                                         const float* __restrict__ ald,
                                         float* __restrict__ alpha,
                                         float* __restrict__ out,
                                         int w, int lane) {
    int r0 = g_row[w], r1 = g_row[w + 1];
    float4 ad = *(const float4*)&ald[(size_t)w * 4];

    // pass 1: exact max per head (lane-parallel over edges)
    float m0 = -3e38f, m1 = -3e38f, m2 = -3e38f, m3 = -3e38f;
    for (int e = r0 + lane; e < r1; e += 32) {
        int s = g_src[e];
        float4 as4 = *(const float4*)&als[(size_t)s * 4];
        float v0 = as4.x + ad.x; v0 = v0 > 0.f ? v0 : 0.2f * v0;
        float v1 = as4.y + ad.y; v1 = v1 > 0.f ? v1 : 0.2f * v1;
        float v2 = as4.z + ad.z; v2 = v2 > 0.f ? v2 : 0.2f * v2;
        float v3 = as4.w + ad.w; v3 = v3 > 0.f ? v3 : 0.2f * v3;
        m0 = fmaxf(m0, v0); m1 = fmaxf(m1, v1); m2 = fmaxf(m2, v2); m3 = fmaxf(m3, v3);
    }
#pragma unroll
    for (int d = 16; d; d >>= 1) {
        m0 = fmaxf(m0, __shfl_xor_sync(0xffffffffu, m0, d));
        m1 = fmaxf(m1, __shfl_xor_sync(0xffffffffu, m1, d));
        m2 = fmaxf(m2, __shfl_xor_sync(0xffffffffu, m2, d));
        m3 = fmaxf(m3, __shfl_xor_sync(0xffffffffu, m3, d));
    }

    // pass 2: sum of exp; stash unnormalized p in alpha output slot
    float s0 = 0.f, s1 = 0.f, s2 = 0.f, s3 = 0.f;
    for (int e = r0 + lane; e < r1; e += 32) {
        int eid = g_eid[e];
        int s = g_src[e];
        float4 as4 = *(const float4*)&als[(size_t)s * 4];
        float v0 = as4.x + ad.x; v0 = v0 > 0.f ? v0 : 0.2f * v0;
        float v1 = as4.y + ad.y; v1 = v1 > 0.f ? v1 : 0.2f * v1;
        float v2 = as4.z + ad.z; v2 = v2 > 0.f ? v2 : 0.2f * v2;
        float v3 = as4.w + ad.w; v3 = v3 > 0.f ? v3 : 0.2f * v3;
        float p0 = __expf(v0 - m0), p1 = __expf(v1 - m1);
        float p2 = __expf(v2 - m2), p3 = __expf(v3 - m3);
        s0 += p0; s1 += p1; s2 += p2; s3 += p3;
        *(float4*)&alpha[(size_t)eid * 4] = make_float4(p0, p1, p2, p3);
    }
#pragma unroll
    for (int d = 16; d; d >>= 1) {
        s0 += __shfl_xor_sync(0xffffffffu, s0, d);
        s1 += __shfl_xor_sync(0xffffffffu, s1, d);
        s2 += __shfl_xor_sync(0xffffffffu, s2, d);
        s3 += __shfl_xor_sync(0xffffffffu, s3, d);
    }
    float i0 = 1.f / (s0 + 1e-16f), i1 = 1.f / (s1 + 1e-16f);
    float i2 = 1.f / (s2 + 1e-16f), i3 = 1.f / (s3 + 1e-16f);
    __syncwarp();

    // pass 3a: normalize alpha in place (lane-parallel, clean float4 stores)
    for (int e = r0 + lane; e < r1; e += 32) {
        int eid = g_eid[e];
        float4 p = *(const float4*)&alpha[(size_t)eid * 4];
        *(float4*)&alpha[(size_t)eid * 4] =
            make_float4(p.x * i0, p.y * i1, p.z * i2, p.w * i3);
    }
    __syncwarp();

    // pass 3b: aggregate 256 channels, scalar coalesced, unroll 2
    float acc[8] = {0.f, 0.f, 0.f, 0.f, 0.f, 0.f, 0.f, 0.f};
    int e = r0;
    for (; e + 2 <= r1; e += 2) {
        int eidA = g_eid[e],     sA = g_src[e];
        int eidB = g_eid[e + 1], sB = g_src[e + 1];
        float4 pA = *(const float4*)&alpha[(size_t)eidA * 4];
        float4 pB = *(const float4*)&alpha[(size_t)eidB * 4];
        const float* xA = xw + (size_t)sA * 256;
        const float* xB = xw + (size_t)sB * 256;
        acc[0] += pA.x * xA[lane]       + pB.x * xB[lane];
        acc[1] += pA.x * xA[32 + lane]  + pB.x * xB[32 + lane];
        acc[2] += pA.y * xA[64 + lane]  + pB.y * xB[64 + lane];
        acc[3] += pA.y * xA[96 + lane]  + pB.y * xB[96 + lane];
        acc[4] += pA.z * xA[128 + lane] + pB.z * xB[128 + lane];
        acc[5] += pA.z * xA[160 + lane] + pB.z * xB[160 + lane];
        acc[6] += pA.w * xA[192 + lane] + pB.w * xB[192 + lane];
        acc[7] += pA.w * xA[224 + lane] + pB.w * xB[224 + lane];
    }
    if (e < r1) {
        int eid = g_eid[e], s = g_src[e];
        float4 p = *(const float4*)&alpha[(size_t)eid * 4];
        const float* xs = xw + (size_t)s * 256;
        acc[0] += p.x * xs[lane];        acc[1] += p.x * xs[32 + lane];
        acc[2] += p.y * xs[64 + lane];   acc[3] += p.y * xs[96 + lane];
        acc[4] += p.z * xs[128 + lane];  acc[5] += p.z * xs[160 + lane];
        acc[6] += p.w * xs[192 + lane];  acc[7] += p.w * xs[224 + lane];
    }

    if (MODE == 0) {
#pragma unroll
        for (int k = 0; k < 8; k++) {
            int c = k * 32 + lane;
            out[(size_t)w * 256 + c] = fmaxf(acc[k] + bias[c], 0.f);
        }
    } else {
        float u0 = (acc[0] + acc[2] + acc[4] + acc[6]) * 0.25f + bias[lane];
        float u1 = (acc[1] + acc[3] + acc[5] + acc[7]) * 0.25f + bias[32 + lane];
        if (MODE == 1) { u0 = fmaxf(u0, 0.f); u1 = fmaxf(u1, 0.f); }
        out[(size_t)w * 64 + lane]      = u0;
        out[(size_t)w * 64 + 32 + lane] = u1;
    }
}

template <int MODE>
__global__ void k_gat_agg(const float* __restrict__ xw, const float* __restrict__ bias,
                          const float* __restrict__ als, const float* __restrict__ ald,
                          float* __restrict__ alpha, float* __restrict__ out, int n) {
    int w = (blockIdx.x * blockDim.x + threadIdx.x) >> 5;
    int lane = threadIdx.x & 31;
    if (w >= n) return;
    gat_node<MODE>(xw, bias, als, ald, alpha, out, w, lane);
}

__global__ void k_gat_agg_dual(const float* __restrict__ xw0, const float* __restrict__ b0,
                               const float* __restrict__ als0, const float* __restrict__ ald0,
                               float* __restrict__ alpha0, float* __restrict__ out0,
                               const float* __restrict__ xw1, const float* __restrict__ b1,
                               const float* __restrict__ als1, const float* __restrict__ ald1,
                               float* __restrict__ alpha1, float* __restrict__ out1, int n) {
    int w = (blockIdx.x * blockDim.x + threadIdx.x) >> 5;
    int lane = threadIdx.x & 31;
    if (w >= n) return;
    if (blockIdx.y == 0) gat_node<2>(xw0, b0, als0, ald0, alpha0, out0, w, lane);
    else                 gat_node<2>(xw1, b1, als1, ald1, alpha1, out1, w, lane);
}

// ---------------- host ----------------
extern "C" void kernel_launch(void* const* d_in, const int* in_sizes, int n_in,
                              void* d_out, int out_size) {
    int n  = in_sizes[0] / 128;
    int E  = in_sizes[1] / 2;
    int EP = E + n;

    const float* x         = (const float*)d_in[0];
    const int*   ei        = (const int*)d_in[1];
    const float* gcn_W     = (const float*)d_in[2];
    const float* gcn_b     = (const float*)d_in[3];
    const float* gat1_W    = (const float*)d_in[4];
    const float* gat1_asrc = (const float*)d_in[5];
    const float* gat1_adst = (const float*)d_in[6];
    const float* gat1_b    = (const float*)d_in[7];
    const float* gat2_W    = (const float*)d_in[8];
    const float* gat2_asrc = (const float*)d_in[9];
    const float* gat2_adst = (const float*)d_in[10];
    const float* gat2_b    = (const float*)d_in[11];
    const float* mean_W    = (const float*)d_in[12];
    const float* mean_asrc = (const float*)d_in[13];
    const float* mean_adst = (const float*)d_in[14];
    const float* mean_b    = (const float*)d_in[15];
    const float* std_W     = (const float*)d_in[16];
    const float* std_asrc  = (const float*)d_in[17];
    const float* std_adst  = (const float*)d_in[18];
    const float* std_b     = (const float*)d_in[19];

    float* out    = (float*)d_out;
    float* z_mean = out;
    float* z_std  = out + (size_t)n * 64;
    float* a1     = out + (size_t)2 * n * 64;
    float* a2     = a1 + (size_t)EP * 4;
    float* am     = a2 + (size_t)EP * 4;
    float* as_    = am + (size_t)EP * 4;

    float *bufA, *bufB, *bufC, *als, *ald, *als2, *ald2;
    cudaGetSymbolAddress((void**)&bufA, g_bufA);
    cudaGetSymbolAddress((void**)&bufB, g_bufB);
    cudaGetSymbolAddress((void**)&bufC, g_bufC);
    cudaGetSymbolAddress((void**)&als,  g_als);
    cudaGetSymbolAddress((void**)&ald,  g_ald);
    cudaGetSymbolAddress((void**)&als2, g_als2);
    cudaGetSymbolAddress((void**)&ald2, g_ald2);

    int gN  = (n + 255) / 256;
    int gEP = (EP + 255) / 256;
    int gW  = (n + 7) / 8;        // warp-per-node kernels, 256 threads
    int gG  = (n + 63) / 64;      // GEMM row blocks (64 rows/block)

    // CSR build (deterministic: rows sorted by edge id)
    k_zero<<<gN, 256>>>(n);
    k_count<<<gEP, 256>>>(ei, E, EP);
    k_scan<<<1, 1024>>>(n);
    k_scatter<<<gEP, 256>>>(ei, E, EP);
    k_sort_fill<<<(n + 127) / 128, 128>>>(ei, E, n);

    // layer 0: GCN (xw prescaled by deg^-1/2 in GEMM epilogue)
    k_gemm64<<<gG, 256>>>(x, gcn_W, bufA, n, 128);
    k_gcn_agg<<<gW, 256>>>(bufA, gcn_b, bufB, n);                 // h0 -> bufB [N,64]

    // layer 1: GAT concat
    k_gemm256tc<0><<<gG, 256>>>(bufB, gat1_W, nullptr, bufA, nullptr, n, 64);
    k_prep<<<gW, 256>>>(bufA, gat1_asrc, gat1_adst, als, ald, n);
    k_gat_agg<0><<<gW, 256>>>(bufA, gat1_b, als, ald, a1, bufC, n);   // h1 -> bufC [N,256]

    // layer 2: GAT mean + relu
    k_gemm256tc<0><<<gG, 256>>>(bufC, gat2_W, nullptr, bufA, nullptr, n, 256);
    k_prep<<<gW, 256>>>(bufA, gat2_asrc, gat2_adst, als, ald, n);
    k_gat_agg<1><<<gW, 256>>>(bufA, gat2_b, als, ald, a2, bufB, n);   // h2 -> bufB [N,64]

    // fused mean + std heads (independent -> batched via blockIdx.y)
    dim3 gridG2(gG, 2), gridW2(gW, 2);
    k_gemm256tc<1><<<gridG2, 256>>>(bufB, mean_W, std_W, bufA, bufC, n, 64);
    k_prep_dual<<<gridW2, 256>>>(bufA, mean_asrc, mean_adst, als, ald,
                                 bufC, std_asrc,  std_adst,  als2, ald2, n);
    k_gat_agg_dual<<<gridW2, 256>>>(bufA, mean_b, als, ald, am,  z_mean,
                                    bufC, std_b,  als2, ald2, as_, z_std, n);
}

// round 10
// speedup vs baseline: 2.0813x; 2.0813x over previous
#include <cuda_runtime.h>

#define MAXN 20000
#define MAXE 320000
#define MAXEP (MAXN + MAXE)

// ---------------- scratch (no allocs allowed) ----------------
__device__ int   g_deg[MAXN];
__device__ int   g_row[MAXN + 1];
__device__ int   g_cur[MAXN];
__device__ int   g_eid[MAXEP];
__device__ int   g_src[MAXEP];
__device__ float g_dis[MAXN];
__device__ __align__(16) float g_als[MAXN * 4];
__device__ __align__(16) float g_ald[MAXN * 4];
__device__ __align__(16) float g_als2[MAXN * 4];
__device__ __align__(16) float g_ald2[MAXN * 4];
__device__ __align__(16) float g_bufA[MAXN * 256];
__device__ __align__(16) float g_bufB[MAXN * 256];
__device__ __align__(16) float g_bufC[MAXN * 256];
__device__ __align__(16) float g_wfA[131072];   // fragment-major W (hi/lo), K<=256
__device__ __align__(16) float g_wfB[131072];

// ---------------- CSR build ----------------
__global__ void k_zero(int n) {
    int i = blockIdx.x * blockDim.x + threadIdx.x;
    if (i < n) g_deg[i] = 0;
}

__global__ void k_count(const int* __restrict__ ei, int E, int EP) {
    int i = blockIdx.x * blockDim.x + threadIdx.x;
    if (i < EP) {
        int d = (i < E) ? ei[E + i] : (i - E);
        atomicAdd(&g_deg[d], 1);
    }
}

__global__ __launch_bounds__(1024) void k_scan(int n) {
    __shared__ int wsum[32];
    int tid = threadIdx.x;
    int per = (n + 1023) >> 10;
    int start = tid * per;
    int end = min(start + per, n);

    int sum = 0;
    for (int i = start; i < end; i++) sum += g_deg[i];

    int lane = tid & 31, wid = tid >> 5;
    int v = sum;
#pragma unroll
    for (int d = 1; d < 32; d <<= 1) {
        int t = __shfl_up_sync(0xffffffffu, v, d);
        if (lane >= d) v += t;
    }
    if (lane == 31) wsum[wid] = v;
    __syncthreads();
    if (wid == 0) {
        int u = wsum[lane];
#pragma unroll
        for (int d = 1; d < 32; d <<= 1) {
            int t = __shfl_up_sync(0xffffffffu, u, d);
            if (lane >= d) u += t;
        }
        wsum[lane] = u;
    }
    __syncthreads();

    int off = v - sum + (wid ? wsum[wid - 1] : 0);
    int run = off;
    for (int i = start; i < end; i++) {
        int dv = g_deg[i];
        g_cur[i] = run;
        run += dv;
        g_row[i + 1] = run;
        g_dis[i] = rsqrtf((float)dv);
    }
    if (tid == 0) g_row[0] = 0;
}

__global__ void k_scatter(const int* __restrict__ ei, int E, int EP) {
    int i = blockIdx.x * blockDim.x + threadIdx.x;
    if (i < EP) {
        int d = (i < E) ? ei[E + i] : (i - E);
        int pos = atomicAdd(&g_cur[d], 1);
        g_eid[pos] = i;
    }
}

__global__ void k_sort_fill(const int* __restrict__ ei, int E, int n) {
    int i = blockIdx.x * blockDim.x + threadIdx.x;
    if (i >= n) return;
    int r0 = g_row[i], r1 = g_row[i + 1];
    for (int a = r0 + 1; a < r1; a++) {
        int v = g_eid[a];
        int b = a - 1;
        while (b >= r0 && g_eid[b] > v) { g_eid[b + 1] = g_eid[b]; b--; }
        g_eid[b + 1] = v;
    }
    for (int e = r0; e < r1; e++) {
        int eid = g_eid[e];
        g_src[e] = (eid < E) ? ei[eid] : (eid - E);
    }
}

// ---------------- tensor-core GEMM (3xTF32, pre-fragmented W) ----------------
__device__ __forceinline__ unsigned cvt_tf32(float x) {
    unsigned r;
    asm("cvt.rna.tf32.f32 %0, %1;" : "=r"(r) : "f"(x));
    return r;
}

#define MMA_TF32(D, A0, A1, A2, A3, B0, B1)                                  \
    asm volatile(                                                            \
        "mma.sync.aligned.m16n8k8.row.col.f32.tf32.tf32.f32 "                \
        "{%0,%1,%2,%3}, {%4,%5,%6,%7}, {%8,%9}, {%0,%1,%2,%3};"              \
        : "+f"(D[0]), "+f"(D[1]), "+f"(D[2]), "+f"(D[3])                     \
        : "r"(A0), "r"(A1), "r"(A2), "r"(A3), "r"(B0), "r"(B1))

// Convert W[K,256] into fragment-major hi/lo layout:
// per k0-chunk(16 k) : [k8(2)][wc(2)][n8(16)][lane(32)] x float4 (b0h,b1h,b0l,b1l)
__global__ void k_prepW(const float* __restrict__ W, float* __restrict__ Wf, int K) {
    int idx = blockIdx.x * blockDim.x + threadIdx.x;
    if (idx >= K * 256) return;
    int k = idx >> 8, n = idx & 255;
    float x = W[idx];
    unsigned h = cvt_tf32(x);
    unsigned l = cvt_tf32(x - __uint_as_float(h));
    int k0c = k >> 4, kr = k & 15, k8 = kr >> 3, kk = kr & 7;
    int tig = kk & 3, pslot = kk >> 2;
    int wc = n >> 7, nn = n & 127, n8 = nn >> 3, gid = nn & 7;
    int lane = gid * 4 + tig;
    int base = k0c * 8192 + (((k8 * 2 + wc) * 16 + n8) * 128) + lane * 4;
    Wf[base + pslot]     = __uint_as_float(h);
    Wf[base + 2 + pslot] = __uint_as_float(l);
}

// C[M,256] = A[M,K] @ W[K,256], W pre-fragmented. 256 thr, 64-row tile.
template <int DUAL>
__global__ __launch_bounds__(256) void k_gemm256tc(const float* __restrict__ A,
                                                   const float* __restrict__ Wf0,
                                                   const float* __restrict__ Wf1,
                                                   float* __restrict__ C0,
                                                   float* __restrict__ C1,
                                                   int M, int K) {
    const float* Wf = (DUAL && blockIdx.y) ? Wf1 : Wf0;
    float*       C  = (DUAL && blockIdx.y) ? C1  : C0;

    __shared__ float As[64 * 20];     // pad 20: conflict-free fragment reads
    __shared__ float Bf[8192];        // one k0-chunk of fragment-major W

    int tid = threadIdx.x, lane = tid & 31, w = tid >> 5;
    int gid = lane >> 2, tig = lane & 3;
    int wr = w & 3, wc = w >> 2;
    int row0 = blockIdx.x * 64;

    float d[16][4];
#pragma unroll
    for (int i = 0; i < 16; i++)
#pragma unroll
        for (int j = 0; j < 4; j++) d[i][j] = 0.f;

    int arow = tid >> 2, akq = tid & 3;
    int nchunk = K >> 4;

    for (int c = 0; c < nchunk; c++) {
        // stage A tile (coalesced)
        float4 av = make_float4(0.f, 0.f, 0.f, 0.f);
        if (row0 + arow < M)
            av = *(const float4*)(A + (size_t)(row0 + arow) * K + c * 16 + akq * 4);
        *(float4*)&As[arow * 20 + akq * 4] = av;
        // stage B fragments (linear copy, conflict-free)
        const float4* src = (const float4*)(Wf + c * 8192);
        float4* dst = (float4*)Bf;
#pragma unroll
        for (int t = 0; t < 8; t++) dst[tid + t * 256] = src[tid + t * 256];
        __syncthreads();

#pragma unroll
        for (int k8 = 0; k8 < 2; k8++) {
            float f0 = As[(wr * 16 + gid) * 20 + k8 * 8 + tig];
            float f1 = As[(wr * 16 + gid + 8) * 20 + k8 * 8 + tig];
            float f2 = As[(wr * 16 + gid) * 20 + k8 * 8 + tig + 4];
            float f3 = As[(wr * 16 + gid + 8) * 20 + k8 * 8 + tig + 4];
            unsigned a0h = cvt_tf32(f0), a1h = cvt_tf32(f1);
            unsigned a2h = cvt_tf32(f2), a3h = cvt_tf32(f3);
            unsigned a0l = cvt_tf32(f0 - __uint_as_float(a0h));
            unsigned a1l = cvt_tf32(f1 - __uint_as_float(a1h));
            unsigned a2l = cvt_tf32(f2 - __uint_as_float(a2h));
            unsigned a3l = cvt_tf32(f3 - __uint_as_float(a3h));
#pragma unroll
            for (int n8 = 0; n8 < 16; n8++) {
                float4 bb = *(const float4*)
                    &Bf[(((k8 * 2 + wc) * 16 + n8) * 128) + lane * 4];
                unsigned b0h = __float_as_uint(bb.x), b1h = __float_as_uint(bb.y);
                unsigned b0l = __float_as_uint(bb.z), b1l = __float_as_uint(bb.w);
                MMA_TF32(d[n8], a0h, a1h, a2h, a3h, b0h, b1h);
                MMA_TF32(d[n8], a0l, a1l, a2l, a3l, b0h, b1h);
                MMA_TF32(d[n8], a0h, a1h, a2h, a3h, b0l, b1l);
            }
        }
        __syncthreads();
    }

    int ra = row0 + wr * 16 + gid;
    int rb = ra + 8;
#pragma unroll
    for (int n8 = 0; n8 < 16; n8++) {
        int col = wc * 128 + n8 * 8 + tig * 2;
        if (ra < M) *(float2*)&C[(size_t)ra * 256 + col] = make_float2(d[n8][0], d[n8][1]);
        if (rb < M) *(float2*)&C[(size_t)rb * 256 + col] = make_float2(d[n8][2], d[n8][3]);
    }
}

// C[M,64] = dis[r] * (A[M,K] @ W[K,64])  (FFMA; small)
__global__ __launch_bounds__(256) void k_gemm64(const float* __restrict__ A,
                                                const float* __restrict__ W,
                                                float* __restrict__ C, int M, int K) {
    __shared__ float Ash[64][36];
    __shared__ float Wsh[32][64];
    int tid = threadIdx.x;
    int x = tid & 15, y = tid >> 4;
    int row0 = blockIdx.x * 64;
    float acc[4][4];
#pragma unroll
    for (int i = 0; i < 4; i++)
#pragma unroll
        for (int j = 0; j < 4; j++) acc[i][j] = 0.f;

    for (int k0 = 0; k0 < K; k0 += 32) {
#pragma unroll
        for (int t = 0; t < 2; t++) {
            int idx = tid + t * 256;
            int r = idx >> 3, kq = idx & 7;
            int grow = row0 + r;
            float4 v = make_float4(0.f, 0.f, 0.f, 0.f);
            if (grow < M) v = *(const float4*)(A + (size_t)grow * K + k0 + kq * 4);
            *(float4*)&Ash[r][kq * 4] = v;
        }
#pragma unroll
        for (int t = 0; t < 2; t++) {
            int idx = tid + t * 256;
            int kr = idx >> 4, cq = idx & 15;
            *(float4*)&Wsh[kr][cq * 4] = *(const float4*)(W + (size_t)(k0 + kr) * 64 + cq * 4);
        }
        __syncthreads();
#pragma unroll
        for (int k = 0; k < 32; k++) {
            float a[4];
#pragma unroll
            for (int i = 0; i < 4; i++) a[i] = Ash[y + 16 * i][k];
            float4 wv = *(float4*)&Wsh[k][x * 4];
#pragma unroll
            for (int i = 0; i < 4; i++) {
                acc[i][0] += a[i] * wv.x; acc[i][1] += a[i] * wv.y;
                acc[i][2] += a[i] * wv.z; acc[i][3] += a[i] * wv.w;
            }
        }
        __syncthreads();
    }
#pragma unroll
    for (int i = 0; i < 4; i++) {
        int r = row0 + y + 16 * i;
        if (r < M) {
            float di = g_dis[r];
            *(float4*)(C + (size_t)r * 64 + x * 4) =
                make_float4(di * acc[i][0], di * acc[i][1], di * acc[i][2], di * acc[i][3]);
        }
    }
}

// ---------------- GCN aggregate ----------------
__global__ void k_gcn_agg(const float* __restrict__ xw, const float* __restrict__ bias,
                          float* __restrict__ out, int n) {
    int w = (blockIdx.x * blockDim.x + threadIdx.x) >> 5;
    int lane = threadIdx.x & 31;
    if (w >= n) return;
    int r0 = g_row[w], r1 = g_row[w + 1];
    const float2* x2 = (const float2*)xw;
    float ax = 0.f, ay = 0.f;
    int e = r0;
    for (; e + 2 <= r1; e += 2) {
        int s0 = g_src[e], s1 = g_src[e + 1];
        float2 v0 = x2[(size_t)s0 * 32 + lane];
        float2 v1 = x2[(size_t)s1 * 32 + lane];
        ax += v0.x + v1.x; ay += v0.y + v1.y;
    }
    if (e < r1) {
        int s = g_src[e];
        float2 v = x2[(size_t)s * 32 + lane];
        ax += v.x; ay += v.y;
    }
    float di = g_dis[w];
    float2 b = ((const float2*)bias)[lane];
    ((float2*)out)[(size_t)w * 32 + lane] =
        make_float2(fmaxf(di * ax + b.x, 0.f), fmaxf(di * ay + b.y, 0.f));
}

// ---------------- attention prep ----------------
__device__ __forceinline__ void prep_node(const float* __restrict__ xw,
                                          const float* __restrict__ asrc,
                                          const float* __restrict__ adst,
                                          float* __restrict__ als,
                                          float* __restrict__ ald,
                                          int w, int lane) {
    const float4* xv = (const float4*)(xw + (size_t)w * 256);
    float4 x0 = xv[lane * 2], x1 = xv[lane * 2 + 1];
    const float4* sv = (const float4*)asrc;
    const float4* dv = (const float4*)adst;
    float4 a0 = sv[lane * 2], a1 = sv[lane * 2 + 1];
    float4 b0 = dv[lane * 2], b1 = dv[lane * 2 + 1];
    float ss = x0.x * a0.x + x0.y * a0.y + x0.z * a0.z + x0.w * a0.w
             + x1.x * a1.x + x1.y * a1.y + x1.z * a1.z + x1.w * a1.w;
    float dd = x0.x * b0.x + x0.y * b0.y + x0.z * b0.z + x0.w * b0.w
             + x1.x * b1.x + x1.y * b1.y + x1.z * b1.z + x1.w * b1.w;
#pragma unroll
    for (int d = 4; d; d >>= 1) {
        ss += __shfl_down_sync(0xffffffffu, ss, d);
        dd += __shfl_down_sync(0xffffffffu, dd, d);
    }
    if ((lane & 7) == 0) {
        int h = lane >> 3;
        als[(size_t)w * 4 + h] = ss;
        ald[(size_t)w * 4 + h] = dd;
    }
}

__global__ void k_prep(const float* __restrict__ xw, const float* __restrict__ asrc,
                       const float* __restrict__ adst, float* __restrict__ als,
                       float* __restrict__ ald, int n) {
    int w = (blockIdx.x * blockDim.x + threadIdx.x) >> 5;
    int lane = threadIdx.x & 31;
    if (w >= n) return;
    prep_node(xw, asrc, adst, als, ald, w, lane);
}

__global__ void k_prep_dual(const float* __restrict__ xw0, const float* __restrict__ a0s,
                            const float* __restrict__ a0d, float* __restrict__ als0,
                            float* __restrict__ ald0,
                            const float* __restrict__ xw1, const float* __restrict__ a1s,
                            const float* __restrict__ a1d, float* __restrict__ als1,
                            float* __restrict__ ald1, int n) {
    int w = (blockIdx.x * blockDim.x + threadIdx.x) >> 5;
    int lane = threadIdx.x & 31;
    if (w >= n) return;
    if (blockIdx.y == 0) prep_node(xw0, a0s, a0d, als0, ald0, w, lane);
    else                 prep_node(xw1, a1s, a1d, als1, ald1, w, lane);
}

// ---------------- GAT aggregate ----------------
template <int MODE>
__device__ __forceinline__ void gat_node(const float* __restrict__ xw,
                                         const float* __restrict__ bias,
                                         const float* __restrict__ als,
                                         const float* __restrict__ ald,
                                         float* __restrict__ alpha,
                                         float* __restrict__ out,
                                         int w, int lane) {
    int r0 = g_row[w], r1 = g_row[w + 1];
    float4 ad = *(const float4*)&ald[(size_t)w * 4];

    float m0 = -3e38f, m1 = -3e38f, m2 = -3e38f, m3 = -3e38f;
    for (int e = r0 + lane; e < r1; e += 32) {
        int s = g_src[e];
        float4 as4 = *(const float4*)&als[(size_t)s * 4];
        float v0 = as4.x + ad.x; v0 = v0 > 0.f ? v0 : 0.2f * v0;
        float v1 = as4.y + ad.y; v1 = v1 > 0.f ? v1 : 0.2f * v1;
        float v2 = as4.z + ad.z; v2 = v2 > 0.f ? v2 : 0.2f * v2;
        float v3 = as4.w + ad.w; v3 = v3 > 0.f ? v3 : 0.2f * v3;
        m0 = fmaxf(m0, v0); m1 = fmaxf(m1, v1); m2 = fmaxf(m2, v2); m3 = fmaxf(m3, v3);
    }
#pragma unroll
    for (int d = 16; d; d >>= 1) {
        m0 = fmaxf(m0, __shfl_xor_sync(0xffffffffu, m0, d));
        m1 = fmaxf(m1, __shfl_xor_sync(0xffffffffu, m1, d));
        m2 = fmaxf(m2, __shfl_xor_sync(0xffffffffu, m2, d));
        m3 = fmaxf(m3, __shfl_xor_sync(0xffffffffu, m3, d));
    }

    float s0 = 0.f, s1 = 0.f, s2 = 0.f, s3 = 0.f;
    for (int e = r0 + lane; e < r1; e += 32) {
        int eid = g_eid[e];
        int s = g_src[e];
        float4 as4 = *(const float4*)&als[(size_t)s * 4];
        float v0 = as4.x + ad.x; v0 = v0 > 0.f ? v0 : 0.2f * v0;
        float v1 = as4.y + ad.y; v1 = v1 > 0.f ? v1 : 0.2f * v1;
        float v2 = as4.z + ad.z; v2 = v2 > 0.f ? v2 : 0.2f * v2;
        float v3 = as4.w + ad.w; v3 = v3 > 0.f ? v3 : 0.2f * v3;
        float p0 = __expf(v0 - m0), p1 = __expf(v1 - m1);
        float p2 = __expf(v2 - m2), p3 = __expf(v3 - m3);
        s0 += p0; s1 += p1; s2 += p2; s3 += p3;
        *(float4*)&alpha[(size_t)eid * 4] = make_float4(p0, p1, p2, p3);
    }
#pragma unroll
    for (int d = 16; d; d >>= 1) {
        s0 += __shfl_xor_sync(0xffffffffu, s0, d);
        s1 += __shfl_xor_sync(0xffffffffu, s1, d);
        s2 += __shfl_xor_sync(0xffffffffu, s2, d);
        s3 += __shfl_xor_sync(0xffffffffu, s3, d);
    }
    float i0 = 1.f / (s0 + 1e-16f), i1 = 1.f / (s1 + 1e-16f);
    float i2 = 1.f / (s2 + 1e-16f), i3 = 1.f / (s3 + 1e-16f);
    __syncwarp();

    for (int e = r0 + lane; e < r1; e += 32) {
        int eid = g_eid[e];
        float4 p = *(const float4*)&alpha[(size_t)eid * 4];
        *(float4*)&alpha[(size_t)eid * 4] =
            make_float4(p.x * i0, p.y * i1, p.z * i2, p.w * i3);
    }
    __syncwarp();

    float acc[8] = {0.f, 0.f, 0.f, 0.f, 0.f, 0.f, 0.f, 0.f};
    int e = r0;
    for (; e + 2 <= r1; e += 2) {
        int eidA = g_eid[e],     sA = g_src[e];
        int eidB = g_eid[e + 1], sB = g_src[e + 1];
        float4 pA = *(const float4*)&alpha[(size_t)eidA * 4];
        float4 pB = *(const float4*)&alpha[(size_t)eidB * 4];
        const float* xA = xw + (size_t)sA * 256;
        const float* xB = xw + (size_t)sB * 256;
        acc[0] += pA.x * xA[lane]       + pB.x * xB[lane];
        acc[1] += pA.x * xA[32 + lane]  + pB.x * xB[32 + lane];
        acc[2] += pA.y * xA[64 + lane]  + pB.y * xB[64 + lane];
        acc[3] += pA.y * xA[96 + lane]  + pB.y * xB[96 + lane];
        acc[4] += pA.z * xA[128 + lane] + pB.z * xB[128 + lane];
        acc[5] += pA.z * xA[160 + lane] + pB.z * xB[160 + lane];
        acc[6] += pA.w * xA[192 + lane] + pB.w * xB[192 + lane];
        acc[7] += pA.w * xA[224 + lane] + pB.w * xB[224 + lane];
    }
    if (e < r1) {
        int eid = g_eid[e], s = g_src[e];
        float4 p = *(const float4*)&alpha[(size_t)eid * 4];
        const float* xs = xw + (size_t)s * 256;
        acc[0] += p.x * xs[lane];        acc[1] += p.x * xs[32 + lane];
        acc[2] += p.y * xs[64 + lane];   acc[3] += p.y * xs[96 + lane];
        acc[4] += p.z * xs[128 + lane];  acc[5] += p.z * xs[160 + lane];
        acc[6] += p.w * xs[192 + lane];  acc[7] += p.w * xs[224 + lane];
    }

    if (MODE == 0) {
#pragma unroll
        for (int k = 0; k < 8; k++) {
            int c = k * 32 + lane;
            out[(size_t)w * 256 + c] = fmaxf(acc[k] + bias[c], 0.f);
        }
    } else {
        float u0 = (acc[0] + acc[2] + acc[4] + acc[6]) * 0.25f + bias[lane];
        float u1 = (acc[1] + acc[3] + acc[5] + acc[7]) * 0.25f + bias[32 + lane];
        if (MODE == 1) { u0 = fmaxf(u0, 0.f); u1 = fmaxf(u1, 0.f); }
        out[(size_t)w * 64 + lane]      = u0;
        out[(size_t)w * 64 + 32 + lane] = u1;
    }
}

template <int MODE>
__global__ void k_gat_agg(const float* __restrict__ xw, const float* __restrict__ bias,
                          const float* __restrict__ als, const float* __restrict__ ald,
                          float* __restrict__ alpha, float* __restrict__ out, int n) {
    int w = (blockIdx.x * blockDim.x + threadIdx.x) >> 5;
    int lane = threadIdx.x & 31;
    if (w >= n) return;
    gat_node<MODE>(xw, bias, als, ald, alpha, out, w, lane);
}

__global__ void k_gat_agg_dual(const float* __restrict__ xw0, const float* __restrict__ b0,
                               const float* __restrict__ als0, const float* __restrict__ ald0,
                               float* __restrict__ alpha0, float* __restrict__ out0,
                               const float* __restrict__ xw1, const float* __restrict__ b1,
                               const float* __restrict__ als1, const float* __restrict__ ald1,
                               float* __restrict__ alpha1, float* __restrict__ out1, int n) {
    int w = (blockIdx.x * blockDim.x + threadIdx.x) >> 5;
    int lane = threadIdx.x & 31;
    if (w >= n) return;
    if (blockIdx.y == 0) gat_node<2>(xw0, b0, als0, ald0, alpha0, out0, w, lane);
    else                 gat_node<2>(xw1, b1, als1, ald1, alpha1, out1, w, lane);
}

// ---------------- host ----------------
extern "C" void kernel_launch(void* const* d_in, const int* in_sizes, int n_in,
                              void* d_out, int out_size) {
    int n  = in_sizes[0] / 128;
    int E  = in_sizes[1] / 2;
    int EP = E + n;

    const float* x         = (const float*)d_in[0];
    const int*   ei        = (const int*)d_in[1];
    const float* gcn_W     = (const float*)d_in[2];
    const float* gcn_b     = (const float*)d_in[3];
    const float* gat1_W    = (const float*)d_in[4];
    const float* gat1_asrc = (const float*)d_in[5];
    const float* gat1_adst = (const float*)d_in[6];
    const float* gat1_b    = (const float*)d_in[7];
    const float* gat2_W    = (const float*)d_in[8];
    const float* gat2_asrc = (const float*)d_in[9];
    const float* gat2_adst = (const float*)d_in[10];
    const float* gat2_b    = (const float*)d_in[11];
    const float* mean_W    = (const float*)d_in[12];
    const float* mean_asrc = (const float*)d_in[13];
    const float* mean_adst = (const float*)d_in[14];
    const float* mean_b    = (const float*)d_in[15];
    const float* std_W     = (const float*)d_in[16];
    const float* std_asrc  = (const float*)d_in[17];
    const float* std_adst  = (const float*)d_in[18];
    const float* std_b     = (const float*)d_in[19];

    float* out    = (float*)d_out;
    float* z_mean = out;
    float* z_std  = out + (size_t)n * 64;
    float* a1     = out + (size_t)2 * n * 64;
    float* a2     = a1 + (size_t)EP * 4;
    float* am     = a2 + (size_t)EP * 4;
    float* as_    = am + (size_t)EP * 4;

    float *bufA, *bufB, *bufC, *als, *ald, *als2, *ald2, *wfA, *wfB;
    cudaGetSymbolAddress((void**)&bufA, g_bufA);
    cudaGetSymbolAddress((void**)&bufB, g_bufB);
    cudaGetSymbolAddress((void**)&bufC, g_bufC);
    cudaGetSymbolAddress((void**)&als,  g_als);
    cudaGetSymbolAddress((void**)&ald,  g_ald);
    cudaGetSymbolAddress((void**)&als2, g_als2);
    cudaGetSymbolAddress((void**)&ald2, g_ald2);
    cudaGetSymbolAddress((void**)&wfA,  g_wfA);
    cudaGetSymbolAddress((void**)&wfB,  g_wfB);

    int gN  = (n + 255) / 256;
    int gEP = (EP + 255) / 256;
    int gW  = (n + 7) / 8;
    int gG  = (n + 63) / 64;

    // CSR build
    k_zero<<<gN, 256>>>(n);
    k_count<<<gEP, 256>>>(ei, E, EP);
    k_scan<<<1, 1024>>>(n);
    k_scatter<<<gEP, 256>>>(ei, E, EP);
    k_sort_fill<<<(n + 127) / 128, 128>>>(ei, E, n);

    // layer 0: GCN
    k_gemm64<<<gG, 256>>>(x, gcn_W, bufA, n, 128);
    k_gcn_agg<<<gW, 256>>>(bufA, gcn_b, bufB, n);

    // layer 1: GAT concat
    k_prepW<<<64, 256>>>(gat1_W, wfA, 64);
    k_gemm256tc<0><<<gG, 256>>>(bufB, wfA, nullptr, bufA, nullptr, n, 64);
    k_prep<<<gW, 256>>>(bufA, gat1_asrc, gat1_adst, als, ald, n);
    k_gat_agg<0><<<gW, 256>>>(bufA, gat1_b, als, ald, a1, bufC, n);

    // layer 2: GAT mean + relu
    k_prepW<<<256, 256>>>(gat2_W, wfA, 256);
    k_gemm256tc<0><<<gG, 256>>>(bufC, wfA, nullptr, bufA, nullptr, n, 256);
    k_prep<<<gW, 256>>>(bufA, gat2_asrc, gat2_adst, als, ald, n);
    k_gat_agg<1><<<gW, 256>>>(bufA, gat2_b, als, ald, a2, bufB, n);

    // fused mean + std heads
    k_prepW<<<64, 256>>>(mean_W, wfA, 64);
    k_prepW<<<64, 256>>>(std_W,  wfB, 64);
    dim3 gridG2(gG, 2), gridW2(gW, 2);
    k_gemm256tc<1><<<gridG2, 256>>>(bufB, wfA, wfB, bufA, bufC, n, 64);
    k_prep_dual<<<gridW2, 256>>>(bufA, mean_asrc, mean_adst, als, ald,
                                 bufC, std_asrc,  std_adst,  als2, ald2, n);
    k_gat_agg_dual<<<gridW2, 256>>>(bufA, mean_b, als, ald, am,  z_mean,
                                    bufC, std_b,  als2, ald2, as_, z_std, n);
}

// round 13
// speedup vs baseline: 2.1452x; 1.0307x over previous
#include <cuda_runtime.h>

#define MAXN 20000
#define MAXE 320000
#define MAXEP (MAXN + MAXE)

// ---------------- scratch (no allocs allowed) ----------------
__device__ int   g_deg[MAXN];
__device__ int   g_row[MAXN + 1];
__device__ int   g_cur[MAXN];
__device__ int   g_eid[MAXEP];
__device__ int   g_src[MAXEP];
__device__ float g_dis[MAXN];
__device__ __align__(16) float g_als[MAXN * 4];
__device__ __align__(16) float g_ald[MAXN * 4];
__device__ __align__(16) float g_als2[MAXN * 4];
__device__ __align__(16) float g_ald2[MAXN * 4];
__device__ __align__(16) float g_bufA[MAXN * 256];
__device__ __align__(16) float g_bufB[MAXN * 256];
__device__ __align__(16) float g_bufC[MAXN * 256];
__device__ __align__(16) float g_wfA[131072];   // fragment-major W (hi/lo), K<=256
__device__ __align__(16) float g_wfB[131072];

// ---------------- CSR build ----------------
__global__ void k_zero(int n) {
    int i = blockIdx.x * blockDim.x + threadIdx.x;
    if (i < n) g_deg[i] = 0;
}

__global__ void k_count(const int* __restrict__ ei, int E, int EP) {
    int i = blockIdx.x * blockDim.x + threadIdx.x;
    if (i < EP) {
        int d = (i < E) ? ei[E + i] : (i - E);
        atomicAdd(&g_deg[d], 1);
    }
}

__global__ __launch_bounds__(1024) void k_scan(int n) {
    __shared__ int wsum[32];
    int tid = threadIdx.x;
    int per = (n + 1023) >> 10;
    int start = tid * per;
    int end = min(start + per, n);

    int sum = 0;
    for (int i = start; i < end; i++) sum += g_deg[i];

    int lane = tid & 31, wid = tid >> 5;
    int v = sum;
#pragma unroll
    for (int d = 1; d < 32; d <<= 1) {
        int t = __shfl_up_sync(0xffffffffu, v, d);
        if (lane >= d) v += t;
    }
    if (lane == 31) wsum[wid] = v;
    __syncthreads();
    if (wid == 0) {
        int u = wsum[lane];
#pragma unroll
        for (int d = 1; d < 32; d <<= 1) {
            int t = __shfl_up_sync(0xffffffffu, u, d);
            if (lane >= d) u += t;
        }
        wsum[lane] = u;
    }
    __syncthreads();

    int off = v - sum + (wid ? wsum[wid - 1] : 0);
    int run = off;
    for (int i = start; i < end; i++) {
        int dv = g_deg[i];
        g_cur[i] = run;
        run += dv;
        g_row[i + 1] = run;
        g_dis[i] = rsqrtf((float)dv);
    }
    if (tid == 0) g_row[0] = 0;
}

__global__ void k_scatter(const int* __restrict__ ei, int E, int EP) {
    int i = blockIdx.x * blockDim.x + threadIdx.x;
    if (i < EP) {
        int d = (i < E) ? ei[E + i] : (i - E);
        int pos = atomicAdd(&g_cur[d], 1);
        g_eid[pos] = i;
    }
}

__global__ void k_sort_fill(const int* __restrict__ ei, int E, int n) {
    int i = blockIdx.x * blockDim.x + threadIdx.x;
    if (i >= n) return;
    int r0 = g_row[i], r1 = g_row[i + 1];
    for (int a = r0 + 1; a < r1; a++) {
        int v = g_eid[a];
        int b = a - 1;
        while (b >= r0 && g_eid[b] > v) { g_eid[b + 1] = g_eid[b]; b--; }
        g_eid[b + 1] = v;
    }
    for (int e = r0; e < r1; e++) {
        int eid = g_eid[e];
        g_src[e] = (eid < E) ? ei[eid] : (eid - E);
    }
}

// ---------------- tensor-core GEMM (3xTF32, pre-fragmented W) ----------------
__device__ __forceinline__ unsigned cvt_tf32(float x) {
    unsigned r;
    asm("cvt.rna.tf32.f32 %0, %1;" : "=r"(r) : "f"(x));
    return r;
}

#define MMA_TF32(D, A0, A1, A2, A3, B0, B1)                                  \
    asm volatile(                                                            \
        "mma.sync.aligned.m16n8k8.row.col.f32.tf32.tf32.f32 "                \
        "{%0,%1,%2,%3}, {%4,%5,%6,%7}, {%8,%9}, {%0,%1,%2,%3};"              \
        : "+f"(D[0]), "+f"(D[1]), "+f"(D[2]), "+f"(D[3])                     \
        : "r"(A0), "r"(A1), "r"(A2), "r"(A3), "r"(B0), "r"(B1))

__global__ void k_prepW(const float* __restrict__ W, float* __restrict__ Wf, int K) {
    int idx = blockIdx.x * blockDim.x + threadIdx.x;
    if (idx >= K * 256) return;
    int k = idx >> 8, n = idx & 255;
    float x = W[idx];
    unsigned h = cvt_tf32(x);
    unsigned l = cvt_tf32(x - __uint_as_float(h));
    int k0c = k >> 4, kr = k & 15, k8 = kr >> 3, kk = kr & 7;
    int tig = kk & 3, pslot = kk >> 2;
    int wc = n >> 7, nn = n & 127, n8 = nn >> 3, gid = nn & 7;
    int lane = gid * 4 + tig;
    int base = k0c * 8192 + (((k8 * 2 + wc) * 16 + n8) * 128) + lane * 4;
    Wf[base + pslot]     = __uint_as_float(h);
    Wf[base + 2 + pslot] = __uint_as_float(l);
}

template <int DUAL>
__global__ __launch_bounds__(256) void k_gemm256tc(const float* __restrict__ A,
                                                   const float* __restrict__ Wf0,
                                                   const float* __restrict__ Wf1,
                                                   float* __restrict__ C0,
                                                   float* __restrict__ C1,
                                                   int M, int K) {
    const float* Wf = (DUAL && blockIdx.y) ? Wf1 : Wf0;
    float*       C  = (DUAL && blockIdx.y) ? C1  : C0;

    __shared__ float As[64 * 20];
    __shared__ float Bf[8192];

    int tid = threadIdx.x, lane = tid & 31, w = tid >> 5;
    int gid = lane >> 2, tig = lane & 3;
    int wr = w & 3, wc = w >> 2;
    int row0 = blockIdx.x * 64;

    float d[16][4];
#pragma unroll
    for (int i = 0; i < 16; i++)
#pragma unroll
        for (int j = 0; j < 4; j++) d[i][j] = 0.f;

    int arow = tid >> 2, akq = tid & 3;
    int nchunk = K >> 4;

    for (int c = 0; c < nchunk; c++) {
        float4 av = make_float4(0.f, 0.f, 0.f, 0.f);
        if (row0 + arow < M)
            av = *(const float4*)(A + (size_t)(row0 + arow) * K + c * 16 + akq * 4);
        *(float4*)&As[arow * 20 + akq * 4] = av;
        const float4* src = (const float4*)(Wf + c * 8192);
        float4* dst = (float4*)Bf;
#pragma unroll
        for (int t = 0; t < 8; t++) dst[tid + t * 256] = src[tid + t * 256];
        __syncthreads();

#pragma unroll
        for (int k8 = 0; k8 < 2; k8++) {
            float f0 = As[(wr * 16 + gid) * 20 + k8 * 8 + tig];
            float f1 = As[(wr * 16 + gid + 8) * 20 + k8 * 8 + tig];
            float f2 = As[(wr * 16 + gid) * 20 + k8 * 8 + tig + 4];
            float f3 = As[(wr * 16 + gid + 8) * 20 + k8 * 8 + tig + 4];
            unsigned a0h = cvt_tf32(f0), a1h = cvt_tf32(f1);
            unsigned a2h = cvt_tf32(f2), a3h = cvt_tf32(f3);
            unsigned a0l = cvt_tf32(f0 - __uint_as_float(a0h));
            unsigned a1l = cvt_tf32(f1 - __uint_as_float(a1h));
            unsigned a2l = cvt_tf32(f2 - __uint_as_float(a2h));
            unsigned a3l = cvt_tf32(f3 - __uint_as_float(a3h));
#pragma unroll
            for (int n8 = 0; n8 < 16; n8++) {
                float4 bb = *(const float4*)
                    &Bf[(((k8 * 2 + wc) * 16 + n8) * 128) + lane * 4];
                unsigned b0h = __float_as_uint(bb.x), b1h = __float_as_uint(bb.y);
                unsigned b0l = __float_as_uint(bb.z), b1l = __float_as_uint(bb.w);
                MMA_TF32(d[n8], a0h, a1h, a2h, a3h, b0h, b1h);
                MMA_TF32(d[n8], a0l, a1l, a2l, a3l, b0h, b1h);
                MMA_TF32(d[n8], a0h, a1h, a2h, a3h, b0l, b1l);
            }
        }
        __syncthreads();
    }

    int ra = row0 + wr * 16 + gid;
    int rb = ra + 8;
#pragma unroll
    for (int n8 = 0; n8 < 16; n8++) {
        int col = wc * 128 + n8 * 8 + tig * 2;
        if (ra < M) *(float2*)&C[(size_t)ra * 256 + col] = make_float2(d[n8][0], d[n8][1]);
        if (rb < M) *(float2*)&C[(size_t)rb * 256 + col] = make_float2(d[n8][2], d[n8][3]);
    }
}

// C[M,64] = dis[r] * (A[M,K] @ W[K,64])
__global__ __launch_bounds__(256) void k_gemm64(const float* __restrict__ A,
                                                const float* __restrict__ W,
                                                float* __restrict__ C, int M, int K) {
    __shared__ float Ash[64][36];
    __shared__ float Wsh[32][64];
    int tid = threadIdx.x;
    int x = tid & 15, y = tid >> 4;
    int row0 = blockIdx.x * 64;
    float acc[4][4];
#pragma unroll
    for (int i = 0; i < 4; i++)
#pragma unroll
        for (int j = 0; j < 4; j++) acc[i][j] = 0.f;

    for (int k0 = 0; k0 < K; k0 += 32) {
#pragma unroll
        for (int t = 0; t < 2; t++) {
            int idx = tid + t * 256;
            int r = idx >> 3, kq = idx & 7;
            int grow = row0 + r;
            float4 v = make_float4(0.f, 0.f, 0.f, 0.f);
            if (grow < M) v = *(const float4*)(A + (size_t)grow * K + k0 + kq * 4);
            *(float4*)&Ash[r][kq * 4] = v;
        }
#pragma unroll
        for (int t = 0; t < 2; t++) {
            int idx = tid + t * 256;
            int kr = idx >> 4, cq = idx & 15;
            *(float4*)&Wsh[kr][cq * 4] = *(const float4*)(W + (size_t)(k0 + kr) * 64 + cq * 4);
        }
        __syncthreads();
#pragma unroll
        for (int k = 0; k < 32; k++) {
            float a[4];
#pragma unroll
            for (int i = 0; i < 4; i++) a[i] = Ash[y + 16 * i][k];
            float4 wv = *(float4*)&Wsh[k][x * 4];
#pragma unroll
            for (int i = 0; i < 4; i++) {
                acc[i][0] += a[i] * wv.x; acc[i][1] += a[i] * wv.y;
                acc[i][2] += a[i] * wv.z; acc[i][3] += a[i] * wv.w;
            }
        }
        __syncthreads();
    }
#pragma unroll
    for (int i = 0; i < 4; i++) {
        int r = row0 + y + 16 * i;
        if (r < M) {
            float di = g_dis[r];
            *(float4*)(C + (size_t)r * 64 + x * 4) =
                make_float4(di * acc[i][0], di * acc[i][1], di * acc[i][2], di * acc[i][3]);
        }
    }
}

// ---------------- GCN aggregate ----------------
__global__ void k_gcn_agg(const float* __restrict__ xw, const float* __restrict__ bias,
                          float* __restrict__ out, int n) {
    int w = (blockIdx.x * blockDim.x + threadIdx.x) >> 5;
    int lane = threadIdx.x & 31;
    if (w >= n) return;
    int r0 = g_row[w], r1 = g_row[w + 1];
    const float2* x2 = (const float2*)xw;
    float ax = 0.f, ay = 0.f;
    int e = r0;
    for (; e + 2 <= r1; e += 2) {
        int s0 = g_src[e], s1 = g_src[e + 1];
        float2 v0 = x2[(size_t)s0 * 32 + lane];
        float2 v1 = x2[(size_t)s1 * 32 + lane];
        ax += v0.x + v1.x; ay += v0.y + v1.y;
    }
    if (e < r1) {
        int s = g_src[e];
        float2 v = x2[(size_t)s * 32 + lane];
        ax += v.x; ay += v.y;
    }
    float di = g_dis[w];
    float2 b = ((const float2*)bias)[lane];
    ((float2*)out)[(size_t)w * 32 + lane] =
        make_float2(fmaxf(di * ax + b.x, 0.f), fmaxf(di * ay + b.y, 0.f));
}

// ---------------- attention prep ----------------
__device__ __forceinline__ void prep_node(const float* __restrict__ xw,
                                          const float* __restrict__ asrc,
                                          const float* __restrict__ adst,
                                          float* __restrict__ als,
                                          float* __restrict__ ald,
                                          int w, int lane) {
    const float4* xv = (const float4*)(xw + (size_t)w * 256);
    float4 x0 = xv[lane * 2], x1 = xv[lane * 2 + 1];
    const float4* sv = (const float4*)asrc;
    const float4* dv = (const float4*)adst;
    float4 a0 = sv[lane * 2], a1 = sv[lane * 2 + 1];
    float4 b0 = dv[lane * 2], b1 = dv[lane * 2 + 1];
    float ss = x0.x * a0.x + x0.y * a0.y + x0.z * a0.z + x0.w * a0.w
             + x1.x * a1.x + x1.y * a1.y + x1.z * a1.z + x1.w * a1.w;
    float dd = x0.x * b0.x + x0.y * b0.y + x0.z * b0.z + x0.w * b0.w
             + x1.x * b1.x + x1.y * b1.y + x1.z * b1.z + x1.w * b1.w;
#pragma unroll
    for (int d = 4; d; d >>= 1) {
        ss += __shfl_down_sync(0xffffffffu, ss, d);
        dd += __shfl_down_sync(0xffffffffu, dd, d);
    }
    if ((lane & 7) == 0) {
        int h = lane >> 3;
        als[(size_t)w * 4 + h] = ss;
        ald[(size_t)w * 4 + h] = dd;
    }
}

__global__ void k_prep(const float* __restrict__ xw, const float* __restrict__ asrc,
                       const float* __restrict__ adst, float* __restrict__ als,
                       float* __restrict__ ald, int n) {
    int w = (blockIdx.x * blockDim.x + threadIdx.x) >> 5;
    int lane = threadIdx.x & 31;
    if (w >= n) return;
    prep_node(xw, asrc, adst, als, ald, w, lane);
}

__global__ void k_prep_dual(const float* __restrict__ xw0, const float* __restrict__ a0s,
                            const float* __restrict__ a0d, float* __restrict__ als0,
                            float* __restrict__ ald0,
                            const float* __restrict__ xw1, const float* __restrict__ a1s,
                            const float* __restrict__ a1d, float* __restrict__ als1,
                            float* __restrict__ ald1, int n) {
    int w = (blockIdx.x * blockDim.x + threadIdx.x) >> 5;
    int lane = threadIdx.x & 31;
    if (w >= n) return;
    if (blockIdx.y == 0) prep_node(xw0, a0s, a0d, als0, ald0, w, lane);
    else                 prep_node(xw1, a1s, a1d, als1, ald1, w, lane);
}

// ---------------- GAT aggregate ----------------
// MODE 0: concat(256)+bias+relu ; MODE 1: head-mean+bias+relu ; MODE 2: head-mean+bias
template <int MODE>
__device__ __forceinline__ void gat_node(const float* __restrict__ xw,
                                         const float* __restrict__ bias,
                                         const float* __restrict__ als,
                                         const float* __restrict__ ald,
                                         float* __restrict__ alpha,
                                         float* __restrict__ out,
                                         int w, int lane) {
    int r0 = g_row[w], r1 = g_row[w + 1];
    float4 ad = *(const float4*)&ald[(size_t)w * 4];

    // pass 1: exact max per head
    float m0 = -3e38f, m1 = -3e38f, m2 = -3e38f, m3 = -3e38f;
    for (int e = r0 + lane; e < r1; e += 32) {
        int s = g_src[e];
        float4 as4 = *(const float4*)&als[(size_t)s * 4];
        float v0 = as4.x + ad.x; v0 = v0 > 0.f ? v0 : 0.2f * v0;
        float v1 = as4.y + ad.y; v1 = v1 > 0.f ? v1 : 0.2f * v1;
        float v2 = as4.z + ad.z; v2 = v2 > 0.f ? v2 : 0.2f * v2;
        float v3 = as4.w + ad.w; v3 = v3 > 0.f ? v3 : 0.2f * v3;
        m0 = fmaxf(m0, v0); m1 = fmaxf(m1, v1); m2 = fmaxf(m2, v2); m3 = fmaxf(m3, v3);
    }
#pragma unroll
    for (int d = 16; d; d >>= 1) {
        m0 = fmaxf(m0, __shfl_xor_sync(0xffffffffu, m0, d));
        m1 = fmaxf(m1, __shfl_xor_sync(0xffffffffu, m1, d));
        m2 = fmaxf(m2, __shfl_xor_sync(0xffffffffu, m2, d));
        m3 = fmaxf(m3, __shfl_xor_sync(0xffffffffu, m3, d));
    }

    // pass 2: sum of exp; stash unnormalized p
    float s0 = 0.f, s1 = 0.f, s2 = 0.f, s3 = 0.f;
    for (int e = r0 + lane; e < r1; e += 32) {
        int eid = g_eid[e];
        int s = g_src[e];
        float4 as4 = *(const float4*)&als[(size_t)s * 4];
        float v0 = as4.x + ad.x; v0 = v0 > 0.f ? v0 : 0.2f * v0;
        float v1 = as4.y + ad.y; v1 = v1 > 0.f ? v1 : 0.2f * v1;
        float v2 = as4.z + ad.z; v2 = v2 > 0.f ? v2 : 0.2f * v2;
        float v3 = as4.w + ad.w; v3 = v3 > 0.f ? v3 : 0.2f * v3;
        float p0 = __expf(v0 - m0), p1 = __expf(v1 - m1);
        float p2 = __expf(v2 - m2), p3 = __expf(v3 - m3);
        s0 += p0; s1 += p1; s2 += p2; s3 += p3;
        *(float4*)&alpha[(size_t)eid * 4] = make_float4(p0, p1, p2, p3);
    }
#pragma unroll
    for (int d = 16; d; d >>= 1) {
        s0 += __shfl_xor_sync(0xffffffffu, s0, d);
        s1 += __shfl_xor_sync(0xffffffffu, s1, d);
        s2 += __shfl_xor_sync(0xffffffffu, s2, d);
        s3 += __shfl_xor_sync(0xffffffffu, s3, d);
    }
    float i0 = 1.f / (s0 + 1e-16f), i1 = 1.f / (s1 + 1e-16f);
    float i2 = 1.f / (s2 + 1e-16f), i3 = 1.f / (s3 + 1e-16f);
    __syncwarp();

    // pass 3a: normalize alpha in place
    for (int e = r0 + lane; e < r1; e += 32) {
        int eid = g_eid[e];
        float4 p = *(const float4*)&alpha[(size_t)eid * 4];
        *(float4*)&alpha[(size_t)eid * 4] =
            make_float4(p.x * i0, p.y * i1, p.z * i2, p.w * i3);
    }
    __syncwarp();

    // pass 3b: float4 gather. lane holds channels [4*lane..4*lane+3] (acc0:
    // heads 0/1 = ch 0-127) and [128+4*lane..] (acc1: heads 2/3).
    bool hih = lane >= 16;
    const float4* xw4 = (const float4*)xw;
    float4 acc0 = make_float4(0.f, 0.f, 0.f, 0.f);
    float4 acc1 = make_float4(0.f, 0.f, 0.f, 0.f);
    int e = r0;
    for (; e + 2 <= r1; e += 2) {
        int eA = g_eid[e],     sA = g_src[e];
        int eB = g_eid[e + 1], sB = g_src[e + 1];
        float4 pA = *(const float4*)&alpha[(size_t)eA * 4];
        float4 pB = *(const float4*)&alpha[(size_t)eB * 4];
        float waA = hih ? pA.y : pA.x, wbA = hih ? pA.w : pA.z;
        float waB = hih ? pB.y : pB.x, wbB = hih ? pB.w : pB.z;
        float4 vA0 = xw4[(size_t)sA * 64 + lane];
        float4 vA1 = xw4[(size_t)sA * 64 + 32 + lane];
        float4 vB0 = xw4[(size_t)sB * 64 + lane];
        float4 vB1 = xw4[(size_t)sB * 64 + 32 + lane];
        acc0.x += waA * vA0.x + waB * vB0.x;
        acc0.y += waA * vA0.y + waB * vB0.y;
        acc0.z += waA * vA0.z + waB * vB0.z;
        acc0.w += waA * vA0.w + waB * vB0.w;
        acc1.x += wbA * vA1.x + wbB * vB1.x;
        acc1.y += wbA * vA1.y + wbB * vB1.y;
        acc1.z += wbA * vA1.z + wbB * vB1.z;
        acc1.w += wbA * vA1.w + wbB * vB1.w;
    }
    if (e < r1) {
        int eid = g_eid[e], s = g_src[e];
        float4 p = *(const float4*)&alpha[(size_t)eid * 4];
        float wa = hih ? p.y : p.x, wb = hih ? p.w : p.z;
        float4 v0 = xw4[(size_t)s * 64 + lane];
        float4 v1 = xw4[(size_t)s * 64 + 32 + lane];
        acc0.x += wa * v0.x; acc0.y += wa * v0.y;
        acc0.z += wa * v0.z; acc0.w += wa * v0.w;
        acc1.x += wb * v1.x; acc1.y += wb * v1.y;
        acc1.z += wb * v1.z; acc1.w += wb * v1.w;
    }

    if (MODE == 0) {
        float4 b0 = ((const float4*)bias)[lane];
        float4 b1 = ((const float4*)bias)[32 + lane];
        ((float4*)out)[(size_t)w * 64 + lane] =
            make_float4(fmaxf(acc0.x + b0.x, 0.f), fmaxf(acc0.y + b0.y, 0.f),
                        fmaxf(acc0.z + b0.z, 0.f), fmaxf(acc0.w + b0.w, 0.f));
        ((float4*)out)[(size_t)w * 64 + 32 + lane] =
            make_float4(fmaxf(acc1.x + b1.x, 0.f), fmaxf(acc1.y + b1.y, 0.f),
                        fmaxf(acc1.z + b1.z, 0.f), fmaxf(acc1.w + b1.w, 0.f));
    } else {
        // lane l (<16): h0+h2 partials; lane l+16: h1+h3. Fold halves.
        float4 s4 = make_float4(acc0.x + acc1.x, acc0.y + acc1.y,
                                acc0.z + acc1.z, acc0.w + acc1.w);
        s4.x += __shfl_down_sync(0xffffffffu, s4.x, 16);
        s4.y += __shfl_down_sync(0xffffffffu, s4.y, 16);
        s4.z += __shfl_down_sync(0xffffffffu, s4.z, 16);
        s4.w += __shfl_down_sync(0xffffffffu, s4.w, 16);
        if (lane < 16) {
            float4 b = ((const float4*)bias)[lane];
            float4 o = make_float4(s4.x * 0.25f + b.x, s4.y * 0.25f + b.y,
                                   s4.z * 0.25f + b.z, s4.w * 0.25f + b.w);
            if (MODE == 1) {
                o.x = fmaxf(o.x, 0.f); o.y = fmaxf(o.y, 0.f);
                o.z = fmaxf(o.z, 0.f); o.w = fmaxf(o.w, 0.f);
            }
            ((float4*)out)[(size_t)w * 16 + lane] = o;
        }
    }
}

template <int MODE>
__global__ void k_gat_agg(const float* __restrict__ xw, const float* __restrict__ bias,
                          const float* __restrict__ als, const float* __restrict__ ald,
                          float* __restrict__ alpha, float* __restrict__ out, int n) {
    int w = (blockIdx.x * blockDim.x + threadIdx.x) >> 5;
    int lane = threadIdx.x & 31;
    if (w >= n) return;
    gat_node<MODE>(xw, bias, als, ald, alpha, out, w, lane);
}

__global__ void k_gat_agg_dual(const float* __restrict__ xw0, const float* __restrict__ b0,
                               const float* __restrict__ als0, const float* __restrict__ ald0,
                               float* __restrict__ alpha0, float* __restrict__ out0,
                               const float* __restrict__ xw1, const float* __restrict__ b1,
                               const float* __restrict__ als1, const float* __restrict__ ald1,
                               float* __restrict__ alpha1, float* __restrict__ out1, int n) {
    int w = (blockIdx.x * blockDim.x + threadIdx.x) >> 5;
    int lane = threadIdx.x & 31;
    if (w >= n) return;
    if (blockIdx.y == 0) gat_node<2>(xw0, b0, als0, ald0, alpha0, out0, w, lane);
    else                 gat_node<2>(xw1, b1, als1, ald1, alpha1, out1, w, lane);
}

// ---------------- host ----------------
extern "C" void kernel_launch(void* const* d_in, const int* in_sizes, int n_in,
                              void* d_out, int out_size) {
    int n  = in_sizes[0] / 128;
    int E  = in_sizes[1] / 2;
    int EP = E + n;

    const float* x         = (const float*)d_in[0];
    const int*   ei        = (const int*)d_in[1];
    const float* gcn_W     = (const float*)d_in[2];
    const float* gcn_b     = (const float*)d_in[3];
    const float* gat1_W    = (const float*)d_in[4];
    const float* gat1_asrc = (const float*)d_in[5];
    const float* gat1_adst = (const float*)d_in[6];
    const float* gat1_b    = (const float*)d_in[7];
    const float* gat2_W    = (const float*)d_in[8];
    const float* gat2_asrc = (const float*)d_in[9];
    const float* gat2_adst = (const float*)d_in[10];
    const float* gat2_b    = (const float*)d_in[11];
    const float* mean_W    = (const float*)d_in[12];
    const float* mean_asrc = (const float*)d_in[13];
    const float* mean_adst = (const float*)d_in[14];
    const float* mean_b    = (const float*)d_in[15];
    const float* std_W     = (const float*)d_in[16];
    const float* std_asrc  = (const float*)d_in[17];
    const float* std_adst  = (const float*)d_in[18];
    const float* std_b     = (const float*)d_in[19];

    float* out    = (float*)d_out;
    float* z_mean = out;
    float* z_std  = out + (size_t)n * 64;
    float* a1     = out + (size_t)2 * n * 64;
    float* a2     = a1 + (size_t)EP * 4;
    float* am     = a2 + (size_t)EP * 4;
    float* as_    = am + (size_t)EP * 4;

    float *bufA, *bufB, *bufC, *als, *ald, *als2, *ald2, *wfA, *wfB;
    cudaGetSymbolAddress((void**)&bufA, g_bufA);
    cudaGetSymbolAddress((void**)&bufB, g_bufB);
    cudaGetSymbolAddress((void**)&bufC, g_bufC);
    cudaGetSymbolAddress((void**)&als,  g_als);
    cudaGetSymbolAddress((void**)&ald,  g_ald);
    cudaGetSymbolAddress((void**)&als2, g_als2);
    cudaGetSymbolAddress((void**)&ald2, g_ald2);
    cudaGetSymbolAddress((void**)&wfA,  g_wfA);
    cudaGetSymbolAddress((void**)&wfB,  g_wfB);

    int gN  = (n + 255) / 256;
    int gEP = (EP + 255) / 256;
    int gW  = (n + 7) / 8;
    int gG  = (n + 63) / 64;

    // CSR build
    k_zero<<<gN, 256>>>(n);
    k_count<<<gEP, 256>>>(ei, E, EP);
    k_scan<<<1, 1024>>>(n);
    k_scatter<<<gEP, 256>>>(ei, E, EP);
    k_sort_fill<<<(n + 127) / 128, 128>>>(ei, E, n);

    // layer 0: GCN
    k_gemm64<<<gG, 256>>>(x, gcn_W, bufA, n, 128);
    k_gcn_agg<<<gW, 256>>>(bufA, gcn_b, bufB, n);

    // layer 1: GAT concat
    k_prepW<<<64, 256>>>(gat1_W, wfA, 64);
    k_gemm256tc<0><<<gG, 256>>>(bufB, wfA, nullptr, bufA, nullptr, n, 64);
    k_prep<<<gW, 256>>>(bufA, gat1_asrc, gat1_adst, als, ald, n);
    k_gat_agg<0><<<gW, 256>>>(bufA, gat1_b, als, ald, a1, bufC, n);

    // layer 2: GAT mean + relu
    k_prepW<<<256, 256>>>(gat2_W, wfA, 256);
    k_gemm256tc<0><<<gG, 256>>>(bufC, wfA, nullptr, bufA, nullptr, n, 256);
    k_prep<<<gW, 256>>>(bufA, gat2_asrc, gat2_adst, als, ald, n);
    k_gat_agg<1><<<gW, 256>>>(bufA, gat2_b, als, ald, a2, bufB, n);

    // fused mean + std heads
    k_prepW<<<64, 256>>>(mean_W, wfA, 64);
    k_prepW<<<64, 256>>>(std_W,  wfB, 64);
    dim3 gridG2(gG, 2), gridW2(gW, 2);
    k_gemm256tc<1><<<gridG2, 256>>>(bufB, wfA, wfB, bufA, bufC, n, 64);
    k_prep_dual<<<gridW2, 256>>>(bufA, mean_asrc, mean_adst, als, ald,
                                 bufC, std_asrc,  std_adst,  als2, ald2, n);
    k_gat_agg_dual<<<gridW2, 256>>>(bufA, mean_b, als, ald, am,  z_mean,
                                    bufC, std_b,  als2, ald2, as_, z_std, n);
}